// round 5
// baseline (speedup 1.0000x reference)
#include <cuda_runtime.h>
#include <cstdint>

#define NN 30000
#define DMAXX 16

// ---------------- scratch (static device arrays; no cudaMalloc) -------------
__device__ __align__(16) float d_G1[(size_t)NN * 512];    // feat @ Wih1^T + biases
__device__ __align__(16) float d_G2[(size_t)NN * 1024];   // X1 @ Wih2^T + biases
__device__ __align__(16) float d_H1a[(size_t)NN * 128];   // hidden double buffers (perm order)
__device__ __align__(16) float d_H1b[(size_t)NN * 128];
__device__ __align__(16) float d_C1[(size_t)NN * 128];
__device__ __align__(16) float d_H2a[(size_t)NN * 256];
__device__ __align__(16) float d_H2b[(size_t)NN * 256];
__device__ __align__(16) float d_C2[(size_t)NN * 256];
__device__ __align__(16) float d_M1[(size_t)NN * 128];    // aggregated neighbor hidden, natural order
__device__ __align__(16) float d_M2[(size_t)NN * 256];
__device__ __align__(16) float d_X1[(size_t)NN * 256];    // layer-1 output (post relu)
__device__ int d_perm[NN];
__device__ int d_hist[17];
__device__ int d_suffix[18];   // d_suffix[t+1] = #nodes with deg > t
__device__ int d_offset[17];

// ---------------- degree counting sort (descending) -------------------------
__global__ void k_hist_zero() { if (threadIdx.x < 17) d_hist[threadIdx.x] = 0; }
__global__ void k_hist(const int* __restrict__ deg) {
    int n = blockIdx.x * blockDim.x + threadIdx.x;
    if (n < NN) atomicAdd(&d_hist[deg[n]], 1);
}
__global__ void k_scan() {
    d_suffix[17] = 0;
    for (int dd = 16; dd >= 1; --dd) d_suffix[dd] = d_suffix[dd + 1] + d_hist[dd];
    d_suffix[0] = d_suffix[1];
    for (int dd = 1; dd <= 16; ++dd) d_offset[dd] = d_suffix[dd + 1];
}
__global__ void k_scatter(const int* __restrict__ deg) {
    int n = blockIdx.x * blockDim.x + threadIdx.x;
    if (n < NN) {
        int pos = atomicAdd(&d_offset[deg[n]], 1);
        d_perm[pos] = n;
    }
}

// ---------------- zero-init of LSTM states ---------------------------------
__global__ void k_zero_l1() {
    int i = blockIdx.x * blockDim.x + threadIdx.x;
    if (i < NN * 32) {
        ((float4*)d_H1a)[i] = make_float4(0.f, 0.f, 0.f, 0.f);
        ((float4*)d_C1)[i] = make_float4(0.f, 0.f, 0.f, 0.f);
    }
}
__global__ void k_zero_l2() {
    int i = blockIdx.x * blockDim.x + threadIdx.x;
    if (i < NN * 64) {
        ((float4*)d_H2a)[i] = make_float4(0.f, 0.f, 0.f, 0.f);
        ((float4*)d_C2)[i] = make_float4(0.f, 0.f, 0.f, 0.f);
    }
}

// ---------------- tf32 helpers ----------------------------------------------
__device__ __forceinline__ uint32_t f2tf32(float x) {
    uint32_t y;
    asm("cvt.rna.tf32.f32 %0, %1;" : "=r"(y) : "f"(x));
    return y;
}
__device__ __forceinline__ void mma_tf32(float& c0, float& c1, float& c2, float& c3,
                                         uint32_t a0, uint32_t a1, uint32_t a2, uint32_t a3,
                                         uint32_t b0, uint32_t b1) {
    asm volatile(
        "mma.sync.aligned.m16n8k8.row.col.f32.tf32.tf32.f32 "
        "{%0,%1,%2,%3}, {%4,%5,%6,%7}, {%8,%9}, {%0,%1,%2,%3};"
        : "+f"(c0), "+f"(c1), "+f"(c2), "+f"(c3)
        : "r"(a0), "r"(a1), "r"(a2), "r"(a3), "r"(b0), "r"(b1));
}

// ---------------- tf32 GEMM, BK=32, register double-buffered -----------------
// (proven round-4 core) C = A @ W^T (+bias0+bias1) (+=C) (relu)
template<int BM, int BN, int WARPS_M, int WARPS_N, bool ACC, bool RELU>
__global__ __launch_bounds__(256)
void tgemm_nt(const float* __restrict__ A, const float* __restrict__ W,
              const float* __restrict__ bias0, const float* __restrict__ bias1,
              float* __restrict__ C, int M, int Nn, int K) {
    constexpr int BK = 32;
    constexpr int LDS_ = BK + 4;
    constexpr int WM = BM / WARPS_M;
    constexpr int WN = BN / WARPS_N;
    constexpr int MT = WM / 16;
    constexpr int NTT = WN / 8;
    constexpr int NTHR = WARPS_M * WARPS_N * 32;
    constexpr int AIT = BM * (BK / 4) / NTHR;
    constexpr int BIT = BN * (BK / 4) / NTHR;

    int rowBase = blockIdx.y * BM;
    int colBase = blockIdx.x * BN;

    __shared__ uint32_t As[BM * LDS_];
    __shared__ uint32_t Bs[BN * LDS_];

    int tid = threadIdx.x;
    int wid = tid >> 5, lane = tid & 31;
    int wm = wid / WARPS_N, wn = wid % WARPS_N;
    int grp = lane >> 2, tg = lane & 3;

    float acc[MT][NTT][4];
#pragma unroll
    for (int i = 0; i < MT; i++)
#pragma unroll
        for (int j = 0; j < NTT; j++) {
            acc[i][j][0] = 0.f; acc[i][j][1] = 0.f; acc[i][j][2] = 0.f; acc[i][j][3] = 0.f;
        }

    float4 ra[AIT], rb[BIT];
#pragma unroll
    for (int u = 0; u < AIT; u++) {
        int idx = tid + u * NTHR;
        int r = idx / (BK / 4), c4 = (idx % (BK / 4)) * 4;
        int gr = rowBase + r;
        ra[u] = (gr < M) ? *(const float4*)&A[(size_t)gr * K + c4] : make_float4(0.f, 0.f, 0.f, 0.f);
    }
#pragma unroll
    for (int u = 0; u < BIT; u++) {
        int idx = tid + u * NTHR;
        int r = idx / (BK / 4), c4 = (idx % (BK / 4)) * 4;
        rb[u] = *(const float4*)&W[(size_t)(colBase + r) * K + c4];
    }

    for (int k0 = 0; k0 < K; k0 += BK) {
#pragma unroll
        for (int u = 0; u < AIT; u++) {
            int idx = tid + u * NTHR;
            int r = idx / (BK / 4), c4 = (idx % (BK / 4)) * 4;
            uint32_t* dst = &As[r * LDS_ + c4];
            dst[0] = f2tf32(ra[u].x); dst[1] = f2tf32(ra[u].y);
            dst[2] = f2tf32(ra[u].z); dst[3] = f2tf32(ra[u].w);
        }
#pragma unroll
        for (int u = 0; u < BIT; u++) {
            int idx = tid + u * NTHR;
            int r = idx / (BK / 4), c4 = (idx % (BK / 4)) * 4;
            uint32_t* dst = &Bs[r * LDS_ + c4];
            dst[0] = f2tf32(rb[u].x); dst[1] = f2tf32(rb[u].y);
            dst[2] = f2tf32(rb[u].z); dst[3] = f2tf32(rb[u].w);
        }
        __syncthreads();

        int kn = k0 + BK;
        if (kn < K) {
#pragma unroll
            for (int u = 0; u < AIT; u++) {
                int idx = tid + u * NTHR;
                int r = idx / (BK / 4), c4 = (idx % (BK / 4)) * 4;
                int gr = rowBase + r;
                ra[u] = (gr < M) ? *(const float4*)&A[(size_t)gr * K + kn + c4]
                                 : make_float4(0.f, 0.f, 0.f, 0.f);
            }
#pragma unroll
            for (int u = 0; u < BIT; u++) {
                int idx = tid + u * NTHR;
                int r = idx / (BK / 4), c4 = (idx % (BK / 4)) * 4;
                rb[u] = *(const float4*)&W[(size_t)(colBase + r) * K + kn + c4];
            }
        }

#pragma unroll
        for (int kk = 0; kk < BK; kk += 8) {
            uint32_t af[MT][4];
#pragma unroll
            for (int i = 0; i < MT; i++) {
                int r0 = wm * WM + i * 16 + grp;
                int c = kk + tg;
                af[i][0] = As[r0 * LDS_ + c];
                af[i][1] = As[(r0 + 8) * LDS_ + c];
                af[i][2] = As[r0 * LDS_ + c + 4];
                af[i][3] = As[(r0 + 8) * LDS_ + c + 4];
            }
            uint32_t bf[NTT][2];
#pragma unroll
            for (int j = 0; j < NTT; j++) {
                int n0 = wn * WN + j * 8 + grp;
                bf[j][0] = Bs[n0 * LDS_ + kk + tg];
                bf[j][1] = Bs[n0 * LDS_ + kk + tg + 4];
            }
#pragma unroll
            for (int i = 0; i < MT; i++)
#pragma unroll
                for (int j = 0; j < NTT; j++)
                    mma_tf32(acc[i][j][0], acc[i][j][1], acc[i][j][2], acc[i][j][3],
                             af[i][0], af[i][1], af[i][2], af[i][3], bf[j][0], bf[j][1]);
        }
        __syncthreads();
    }

#pragma unroll
    for (int i = 0; i < MT; i++) {
#pragma unroll
        for (int j = 0; j < NTT; j++) {
            int gc = colBase + wn * WN + j * 8 + 2 * tg;
            float b0v = 0.f, b1v = 0.f;
            if (bias0) { b0v += bias0[gc]; b1v += bias0[gc + 1]; }
            if (bias1) { b0v += bias1[gc]; b1v += bias1[gc + 1]; }
            int gr0 = rowBase + wm * WM + i * 16 + grp;
            if (gr0 < M) {
                float v0 = acc[i][j][0] + b0v, v1 = acc[i][j][1] + b1v;
                float* p = &C[(size_t)gr0 * Nn + gc];
                if (ACC) { v0 += p[0]; v1 += p[1]; }
                if (RELU) { v0 = fmaxf(v0, 0.f); v1 = fmaxf(v1, 0.f); }
                *(float2*)p = make_float2(v0, v1);
            }
            int gr1 = gr0 + 8;
            if (gr1 < M) {
                float v0 = acc[i][j][2] + b0v, v1 = acc[i][j][3] + b1v;
                float* p = &C[(size_t)gr1 * Nn + gc];
                if (ACC) { v0 += p[0]; v1 += p[1]; }
                if (RELU) { v0 = fmaxf(v0, 0.f); v1 = fmaxf(v1, 0.f); }
                *(float2*)p = make_float2(v0, v1);
            }
        }
    }
}

// ---------------- fused recurrent LSTM step ----------------------------------
// Same mainloop as tgemm_nt, but B rows gate-grouped (W row = g*H + ub + u) and
// the LSTM pointwise applied in the epilogue. Eliminates the gate-buffer
// round-trip through DRAM. Grid: (H/32, ceil(rows/128)).
__device__ __forceinline__ float sigm_(float x) { return 1.f / (1.f + __expf(-x)); }

template<int H>
__global__ __launch_bounds__(256)
void lstm_fused(const float* __restrict__ Whh, const float* __restrict__ G,
                const float* __restrict__ Hin, float* __restrict__ Hout,
                float* __restrict__ Cst, const int* __restrict__ nbr, int t) {
    constexpr int BM = 128, BN = 128, BK = 32, LDS_ = 36;
    constexpr int WARPS_N = 4;
    constexpr int WM = 64, WN = 32, MT = 4, NTT = 4;
    constexpr int NTHR = 256;
    constexpr int AIT = BM * (BK / 4) / NTHR;   // 4
    constexpr int BIT = BN * (BK / 4) / NTHR;   // 4
    const int K = H;

    __shared__ union SU {
        struct { uint32_t As[BM * LDS_]; uint32_t Bs[BN * LDS_]; } mm;
        float stage[64 * 132];
    } su;

    int rows = d_suffix[t + 1];
    int rowBase = blockIdx.y * BM;
    if (rowBase >= rows) return;
    const int ub = blockIdx.x * 32;   // hidden-unit base

    int tid = threadIdx.x;
    int wid = tid >> 5, lane = tid & 31;
    int wm = wid / WARPS_N, wn = wid % WARPS_N;   // wn == gate index
    int grp = lane >> 2, tg = lane & 3;

    float acc[MT][NTT][4];
#pragma unroll
    for (int i = 0; i < MT; i++)
#pragma unroll
        for (int j = 0; j < NTT; j++) {
            acc[i][j][0] = 0.f; acc[i][j][1] = 0.f; acc[i][j][2] = 0.f; acc[i][j][3] = 0.f;
        }

    float4 ra[AIT], rb[BIT];
#pragma unroll
    for (int u = 0; u < AIT; u++) {
        int idx = tid + u * NTHR;
        int r = idx / (BK / 4), c4 = (idx % (BK / 4)) * 4;
        int gr = rowBase + r;
        ra[u] = (gr < rows) ? *(const float4*)&Hin[(size_t)gr * K + c4] : make_float4(0.f, 0.f, 0.f, 0.f);
    }
#pragma unroll
    for (int u = 0; u < BIT; u++) {
        int idx = tid + u * NTHR;
        int r = idx / (BK / 4), c4 = (idx % (BK / 4)) * 4;
        int wr = (r >> 5) * H + ub + (r & 31);     // gate-grouped W row
        rb[u] = *(const float4*)&Whh[(size_t)wr * K + c4];
    }

    for (int k0 = 0; k0 < K; k0 += BK) {
#pragma unroll
        for (int u = 0; u < AIT; u++) {
            int idx = tid + u * NTHR;
            int r = idx / (BK / 4), c4 = (idx % (BK / 4)) * 4;
            uint32_t* dst = &su.mm.As[r * LDS_ + c4];
            dst[0] = f2tf32(ra[u].x); dst[1] = f2tf32(ra[u].y);
            dst[2] = f2tf32(ra[u].z); dst[3] = f2tf32(ra[u].w);
        }
#pragma unroll
        for (int u = 0; u < BIT; u++) {
            int idx = tid + u * NTHR;
            int r = idx / (BK / 4), c4 = (idx % (BK / 4)) * 4;
            uint32_t* dst = &su.mm.Bs[r * LDS_ + c4];
            dst[0] = f2tf32(rb[u].x); dst[1] = f2tf32(rb[u].y);
            dst[2] = f2tf32(rb[u].z); dst[3] = f2tf32(rb[u].w);
        }
        __syncthreads();

        int kn = k0 + BK;
        if (kn < K) {
#pragma unroll
            for (int u = 0; u < AIT; u++) {
                int idx = tid + u * NTHR;
                int r = idx / (BK / 4), c4 = (idx % (BK / 4)) * 4;
                int gr = rowBase + r;
                ra[u] = (gr < rows) ? *(const float4*)&Hin[(size_t)gr * K + kn + c4]
                                    : make_float4(0.f, 0.f, 0.f, 0.f);
            }
#pragma unroll
            for (int u = 0; u < BIT; u++) {
                int idx = tid + u * NTHR;
                int r = idx / (BK / 4), c4 = (idx % (BK / 4)) * 4;
                int wr = (r >> 5) * H + ub + (r & 31);
                rb[u] = *(const float4*)&Whh[(size_t)wr * K + kn + c4];
            }
        }

#pragma unroll
        for (int kk = 0; kk < BK; kk += 8) {
            uint32_t af[MT][4];
#pragma unroll
            for (int i = 0; i < MT; i++) {
                int r0 = wm * WM + i * 16 + grp;
                int c = kk + tg;
                af[i][0] = su.mm.As[r0 * LDS_ + c];
                af[i][1] = su.mm.As[(r0 + 8) * LDS_ + c];
                af[i][2] = su.mm.As[r0 * LDS_ + c + 4];
                af[i][3] = su.mm.As[(r0 + 8) * LDS_ + c + 4];
            }
            uint32_t bf[NTT][2];
#pragma unroll
            for (int j = 0; j < NTT; j++) {
                int n0 = wn * WN + j * 8 + grp;
                bf[j][0] = su.mm.Bs[n0 * LDS_ + kk + tg];
                bf[j][1] = su.mm.Bs[n0 * LDS_ + kk + tg + 4];
            }
#pragma unroll
            for (int i = 0; i < MT; i++)
#pragma unroll
                for (int j = 0; j < NTT; j++)
                    mma_tf32(acc[i][j][0], acc[i][j][1], acc[i][j][2], acc[i][j][3],
                             af[i][0], af[i][1], af[i][2], af[i][3], bf[j][0], bf[j][1]);
        }
        __syncthreads();
    }

    // epilogue: stage each 64-row half, fuse LSTM pointwise
#pragma unroll 1
    for (int h = 0; h < 2; h++) {
        if (wm == h) {
#pragma unroll
            for (int i = 0; i < MT; i++)
#pragma unroll
                for (int j = 0; j < NTT; j++)
#pragma unroll
                    for (int q = 0; q < 4; q++) {
                        int r = i * 16 + grp + 8 * (q >> 1);
                        int n = wn * 32 + j * 8 + 2 * tg + (q & 1);
                        su.stage[r * 132 + n] = acc[i][j][q];
                    }
        }
        __syncthreads();
#pragma unroll
        for (int it = 0; it < 8; it++) {
            int nl = wid * 8 + it;
            int p = rowBase + h * 64 + nl;
            if (p < rows) {
                int node = d_perm[p];
                int nr = nbr[node * DMAXX + t];
                const float* grow = &G[(size_t)nr * 4 * H + ub + lane];
                float gi = su.stage[nl * 132 + lane]      + grow[0];
                float gf = su.stage[nl * 132 + 32 + lane] + grow[H];
                float gg = su.stage[nl * 132 + 64 + lane] + grow[2 * H];
                float go = su.stage[nl * 132 + 96 + lane] + grow[3 * H];
                size_t off = (size_t)p * H + ub + lane;
                float c = Cst[off];
                c = sigm_(gf) * c + sigm_(gi) * tanhf(gg);
                Cst[off] = c;
                Hout[off] = sigm_(go) * tanhf(c);
            }
        }
        __syncthreads();
    }
}

// ---------------- scatter final hidden (buffer by deg parity) ----------------
__global__ void k_scatter_h1(const int* __restrict__ deg) {
    int idx = blockIdx.x * blockDim.x + threadIdx.x;
    if (idx >= NN * 32) return;
    int p = idx >> 5, lane = idx & 31;
    int node = d_perm[p];
    const float4* src = (deg[node] & 1) ? (const float4*)d_H1b : (const float4*)d_H1a;
    ((float4*)d_M1)[node * 32 + lane] = src[p * 32 + lane];
}
__global__ void k_scatter_h2(const int* __restrict__ deg) {
    int idx = blockIdx.x * blockDim.x + threadIdx.x;
    if (idx >= NN * 64) return;
    int p = idx >> 6, lane = idx & 63;
    int node = d_perm[p];
    const float4* src = (deg[node] & 1) ? (const float4*)d_H2b : (const float4*)d_H2a;
    ((float4*)d_M2)[node * 64 + lane] = src[p * 64 + lane];
}

// ---------------- launch -----------------------------------------------------
extern "C" void kernel_launch(void* const* d_in, const int* in_sizes, int n_in,
                              void* d_out, int out_size) {
    const float* feat    = (const float*)d_in[0];
    const int*   nbr     = (const int*)  d_in[1];
    const int*   deg     = (const int*)  d_in[2];
    const float* Wih1    = (const float*)d_in[3];
    const float* Whh1    = (const float*)d_in[4];
    const float* bih1    = (const float*)d_in[5];
    const float* bhh1    = (const float*)d_in[6];
    const float* Wself1  = (const float*)d_in[7];
    const float* Wneigh1 = (const float*)d_in[8];
    const float* b1      = (const float*)d_in[9];
    const float* Wih2    = (const float*)d_in[10];
    const float* Whh2    = (const float*)d_in[11];
    const float* bih2    = (const float*)d_in[12];
    const float* bhh2    = (const float*)d_in[13];
    const float* Wself2  = (const float*)d_in[14];
    const float* Wneigh2 = (const float*)d_in[15];
    const float* b2      = (const float*)d_in[16];
    float* out = (float*)d_out;

    float *pG1, *pG2, *pH1a, *pH1b, *pC1, *pH2a, *pH2b, *pC2, *pM1, *pM2, *pX1;
    cudaGetSymbolAddress((void**)&pG1, d_G1);
    cudaGetSymbolAddress((void**)&pG2, d_G2);
    cudaGetSymbolAddress((void**)&pH1a, d_H1a);
    cudaGetSymbolAddress((void**)&pH1b, d_H1b);
    cudaGetSymbolAddress((void**)&pC1, d_C1);
    cudaGetSymbolAddress((void**)&pH2a, d_H2a);
    cudaGetSymbolAddress((void**)&pH2b, d_H2b);
    cudaGetSymbolAddress((void**)&pC2, d_C2);
    cudaGetSymbolAddress((void**)&pM1, d_M1);
    cudaGetSymbolAddress((void**)&pM2, d_M2);
    cudaGetSymbolAddress((void**)&pX1, d_X1);

    const int MB = (NN + 127) / 128;  // 235

    k_hist_zero<<<1, 32>>>();
    k_hist<<<(NN + 255) / 256, 256>>>(deg);
    k_scan<<<1, 1>>>();
    k_scatter<<<(NN + 255) / 256, 256>>>(deg);

    // ---------------- layer 1 ----------------
    tgemm_nt<128, 128, 2, 4, false, false><<<dim3(4, MB), 256>>>(
        feat, Wih1, bih1, bhh1, pG1, NN, 512, 128);
    k_zero_l1<<<(NN * 32 + 255) / 256, 256>>>();
    for (int t = 0; t < DMAXX; t++) {
        const float* hin = (t & 1) ? pH1b : pH1a;
        float* hout = (t & 1) ? pH1a : pH1b;
        lstm_fused<128><<<dim3(4, MB), 256>>>(Whh1, pG1, hin, hout, pC1, nbr, t);
    }
    k_scatter_h1<<<(NN * 32 + 255) / 256, 256>>>(deg);
    tgemm_nt<128, 128, 2, 4, false, false><<<dim3(2, MB), 256>>>(
        feat, Wself1, b1, nullptr, pX1, NN, 256, 128);
    tgemm_nt<128, 128, 2, 4, true, true><<<dim3(2, MB), 256>>>(
        pM1, Wneigh1, nullptr, nullptr, pX1, NN, 256, 128);

    // ---------------- layer 2 ----------------
    tgemm_nt<128, 128, 2, 4, false, false><<<dim3(8, MB), 256>>>(
        pX1, Wih2, bih2, bhh2, pG2, NN, 1024, 256);
    k_zero_l2<<<(NN * 64 + 255) / 256, 256>>>();
    for (int t = 0; t < DMAXX; t++) {
        const float* hin = (t & 1) ? pH2b : pH2a;
        float* hout = (t & 1) ? pH2a : pH2b;
        lstm_fused<256><<<dim3(8, MB), 256>>>(Whh2, pG2, hin, hout, pC2, nbr, t);
    }
    k_scatter_h2<<<(NN * 64 + 255) / 256, 256>>>(deg);
    tgemm_nt<128, 64, 2, 4, false, false><<<dim3(1, MB), 256>>>(
        pX1, Wself2, b2, nullptr, out, NN, 64, 256);
    tgemm_nt<128, 64, 2, 4, true, false><<<dim3(1, MB), 256>>>(
        pM2, Wneigh2, nullptr, nullptr, out, NN, 64, 256);
}

// round 6
// speedup vs baseline: 1.4395x; 1.4395x over previous
#include <cuda_runtime.h>
#include <cstdint>

#define NN 30000
#define DMAXX 16

// ---------------- scratch (static device arrays; no cudaMalloc) -------------
__device__ __align__(16) float d_G1[(size_t)NN * 512];    // feat @ Wih1^T + biases
__device__ __align__(16) float d_GB[(size_t)NN * 1024];   // recurrent gate buffer (shared by both layers)
__device__ __align__(16) float d_H1p[(size_t)NN * 128];   // LSTM state, permuted order
__device__ __align__(16) float d_C1p[(size_t)NN * 128];
__device__ __align__(16) float d_M1[(size_t)NN * 128];    // aggregated neighbor hidden, natural order
__device__ __align__(16) float d_X1[(size_t)NN * 256];    // layer-1 output (post relu)
__device__ __align__(16) float d_G2[(size_t)NN * 1024];   // X1 @ Wih2^T + biases
__device__ __align__(16) float d_H2p[(size_t)NN * 256];
__device__ __align__(16) float d_C2p[(size_t)NN * 256];
__device__ __align__(16) float d_M2[(size_t)NN * 256];
__device__ int d_perm[NN];
__device__ int d_hist[17];
__device__ int d_suffix[18];   // d_suffix[t+1] = #nodes with deg > t
__device__ int d_offset[17];

// ---------------- degree counting sort (descending) -------------------------
__global__ void k_hist_zero() { if (threadIdx.x < 17) d_hist[threadIdx.x] = 0; }
__global__ void k_hist(const int* __restrict__ deg) {
    int n = blockIdx.x * blockDim.x + threadIdx.x;
    if (n < NN) atomicAdd(&d_hist[deg[n]], 1);
}
__global__ void k_scan() {
    d_suffix[17] = 0;
    for (int dd = 16; dd >= 1; --dd) d_suffix[dd] = d_suffix[dd + 1] + d_hist[dd];
    d_suffix[0] = d_suffix[1];
    for (int dd = 1; dd <= 16; ++dd) d_offset[dd] = d_suffix[dd + 1];
}
__global__ void k_scatter(const int* __restrict__ deg) {
    int n = blockIdx.x * blockDim.x + threadIdx.x;
    if (n < NN) {
        int pos = atomicAdd(&d_offset[deg[n]], 1);
        d_perm[pos] = n;
    }
}

// ---------------- tf32 helpers ----------------------------------------------
__device__ __forceinline__ uint32_t f2tf32(float x) {
    uint32_t y;
    asm("cvt.rna.tf32.f32 %0, %1;" : "=r"(y) : "f"(x));
    return y;
}
__device__ __forceinline__ void mma_tf32(float& c0, float& c1, float& c2, float& c3,
                                         uint32_t a0, uint32_t a1, uint32_t a2, uint32_t a3,
                                         uint32_t b0, uint32_t b1) {
    asm volatile(
        "mma.sync.aligned.m16n8k8.row.col.f32.tf32.tf32.f32 "
        "{%0,%1,%2,%3}, {%4,%5,%6,%7}, {%8,%9}, {%0,%1,%2,%3};"
        : "+f"(c0), "+f"(c1), "+f"(c2), "+f"(c3)
        : "r"(a0), "r"(a1), "r"(a2), "r"(a3), "r"(b0), "r"(b1));
}

// ---------------- tf32 GEMM: BK=32, reg prefetch + 2-stage smem --------------
// C[M,Nn] = A[M,K] @ W[Nn,K]^T (+bias0+bias1) (+=C) (relu). One sync per tile.
template<int BM, int BN, int WARPS_M, int WARPS_N, bool ACC, bool RELU>
__global__ __launch_bounds__(256)
void tgemm_nt(const float* __restrict__ A, const float* __restrict__ W,
              const float* __restrict__ bias0, const float* __restrict__ bias1,
              float* __restrict__ C, int M, int Nn, int K,
              const int* rowsDev) {
    constexpr int BK = 32;
    constexpr int LDS_ = BK + 4;           // 36, conflict-free fragment reads
    constexpr int WM = BM / WARPS_M;
    constexpr int WN = BN / WARPS_N;
    constexpr int MT = WM / 16;
    constexpr int NTT = WN / 8;
    constexpr int NTHR = WARPS_M * WARPS_N * 32;
    constexpr int AIT = BM * (BK / 4) / NTHR;
    constexpr int BIT = BN * (BK / 4) / NTHR;
    constexpr int ASTRIDE = BM * LDS_;
    constexpr int BSTRIDE = BN * LDS_;

    extern __shared__ uint32_t dynsmem[];
    uint32_t* AsBase = dynsmem;                 // [2][BM*LDS_]
    uint32_t* BsBase = dynsmem + 2 * ASTRIDE;   // [2][BN*LDS_]

    int rows = rowsDev ? *rowsDev : M;
    int rowBase = blockIdx.y * BM;
    if (rowBase >= rows) return;
    int colBase = blockIdx.x * BN;

    int tid = threadIdx.x;
    int wid = tid >> 5, lane = tid & 31;
    int wm = wid / WARPS_N, wn = wid % WARPS_N;
    int grp = lane >> 2, tg = lane & 3;

    float acc[MT][NTT][4];
#pragma unroll
    for (int i = 0; i < MT; i++)
#pragma unroll
        for (int j = 0; j < NTT; j++) {
            acc[i][j][0] = 0.f; acc[i][j][1] = 0.f; acc[i][j][2] = 0.f; acc[i][j][3] = 0.f;
        }

    float4 ra[AIT], rb[BIT];
    // prefetch tile 0 into registers
#pragma unroll
    for (int u = 0; u < AIT; u++) {
        int idx = tid + u * NTHR;
        int r = idx / (BK / 4), c4 = (idx % (BK / 4)) * 4;
        int gr = rowBase + r;
        ra[u] = (gr < rows) ? *(const float4*)&A[(size_t)gr * K + c4]
                            : make_float4(0.f, 0.f, 0.f, 0.f);
    }
#pragma unroll
    for (int u = 0; u < BIT; u++) {
        int idx = tid + u * NTHR;
        int r = idx / (BK / 4), c4 = (idx % (BK / 4)) * 4;
        rb[u] = *(const float4*)&W[(size_t)(colBase + r) * K + c4];
    }

    int stage = 0;
    for (int k0 = 0; k0 < K; k0 += BK, stage ^= 1) {
        uint32_t* As = AsBase + stage * ASTRIDE;
        uint32_t* Bs = BsBase + stage * BSTRIDE;

        // commit current registers (tile k0) to this stage
#pragma unroll
        for (int u = 0; u < AIT; u++) {
            int idx = tid + u * NTHR;
            int r = idx / (BK / 4), c4 = (idx % (BK / 4)) * 4;
            uint32_t* dst = &As[r * LDS_ + c4];
            dst[0] = f2tf32(ra[u].x); dst[1] = f2tf32(ra[u].y);
            dst[2] = f2tf32(ra[u].z); dst[3] = f2tf32(ra[u].w);
        }
#pragma unroll
        for (int u = 0; u < BIT; u++) {
            int idx = tid + u * NTHR;
            int r = idx / (BK / 4), c4 = (idx % (BK / 4)) * 4;
            uint32_t* dst = &Bs[r * LDS_ + c4];
            dst[0] = f2tf32(rb[u].x); dst[1] = f2tf32(rb[u].y);
            dst[2] = f2tf32(rb[u].z); dst[3] = f2tf32(rb[u].w);
        }
        __syncthreads();   // single barrier per tile

        // prefetch next tile (overlaps with MMAs below)
        int kn = k0 + BK;
        if (kn < K) {
#pragma unroll
            for (int u = 0; u < AIT; u++) {
                int idx = tid + u * NTHR;
                int r = idx / (BK / 4), c4 = (idx % (BK / 4)) * 4;
                int gr = rowBase + r;
                ra[u] = (gr < rows) ? *(const float4*)&A[(size_t)gr * K + kn + c4]
                                    : make_float4(0.f, 0.f, 0.f, 0.f);
            }
#pragma unroll
            for (int u = 0; u < BIT; u++) {
                int idx = tid + u * NTHR;
                int r = idx / (BK / 4), c4 = (idx % (BK / 4)) * 4;
                rb[u] = *(const float4*)&W[(size_t)(colBase + r) * K + kn + c4];
            }
        }

#pragma unroll
        for (int kk = 0; kk < BK; kk += 8) {
            uint32_t af[MT][4];
#pragma unroll
            for (int i = 0; i < MT; i++) {
                int r0 = wm * WM + i * 16 + grp;
                int c = kk + tg;
                af[i][0] = As[r0 * LDS_ + c];
                af[i][1] = As[(r0 + 8) * LDS_ + c];
                af[i][2] = As[r0 * LDS_ + c + 4];
                af[i][3] = As[(r0 + 8) * LDS_ + c + 4];
            }
            uint32_t bf[NTT][2];
#pragma unroll
            for (int j = 0; j < NTT; j++) {
                int n0 = wn * WN + j * 8 + grp;
                bf[j][0] = Bs[n0 * LDS_ + kk + tg];
                bf[j][1] = Bs[n0 * LDS_ + kk + tg + 4];
            }
#pragma unroll
            for (int i = 0; i < MT; i++)
#pragma unroll
                for (int j = 0; j < NTT; j++)
                    mma_tf32(acc[i][j][0], acc[i][j][1], acc[i][j][2], acc[i][j][3],
                             af[i][0], af[i][1], af[i][2], af[i][3], bf[j][0], bf[j][1]);
        }
    }

    // epilogue
#pragma unroll
    for (int i = 0; i < MT; i++) {
#pragma unroll
        for (int j = 0; j < NTT; j++) {
            int gc = colBase + wn * WN + j * 8 + 2 * tg;
            float b0v = 0.f, b1v = 0.f;
            if (bias0) { b0v += bias0[gc]; b1v += bias0[gc + 1]; }
            if (bias1) { b0v += bias1[gc]; b1v += bias1[gc + 1]; }
            int gr0 = rowBase + wm * WM + i * 16 + grp;
            if (gr0 < rows) {
                float v0 = acc[i][j][0] + b0v, v1 = acc[i][j][1] + b1v;
                float* p = &C[(size_t)gr0 * Nn + gc];
                if (ACC) { v0 += p[0]; v1 += p[1]; }
                if (RELU) { v0 = fmaxf(v0, 0.f); v1 = fmaxf(v1, 0.f); }
                *(float2*)p = make_float2(v0, v1);
            }
            int gr1 = gr0 + 8;
            if (gr1 < rows) {
                float v0 = acc[i][j][2] + b0v, v1 = acc[i][j][3] + b1v;
                float* p = &C[(size_t)gr1 * Nn + gc];
                if (ACC) { v0 += p[0]; v1 += p[1]; }
                if (RELU) { v0 = fmaxf(v0, 0.f); v1 = fmaxf(v1, 0.f); }
                *(float2*)p = make_float2(v0, v1);
            }
        }
    }
}

// ---------------- LSTM pointwise ---------------------------------------------
__device__ __forceinline__ float sigm_(float x) { return 1.f / (1.f + __expf(-x)); }

// t = 0 step: H=0 so gates come straight from G; no GEMM needed. Writes C, H.
template<int H>
__global__ void lstm_step0(const float* __restrict__ G, const int* __restrict__ nbr,
                           float* __restrict__ Hp, float* __restrict__ Cp) {
    constexpr int TPN = H / 4;
    int cnt = d_suffix[1];
    int idx = blockIdx.x * blockDim.x + threadIdx.x;
    int p = idx / TPN;
    if (p >= cnt) return;
    int lane = idx % TPN;
    int node = d_perm[p];
    int nr = nbr[node * DMAXX];
    const float4* gx = (const float4*)&G[(size_t)nr * 4 * H];
    float4 xi = gx[lane], xg = gx[2 * TPN + lane], xo = gx[3 * TPN + lane];
    float4 c, h;
    c.x = sigm_(xi.x) * tanhf(xg.x); h.x = sigm_(xo.x) * tanhf(c.x);
    c.y = sigm_(xi.y) * tanhf(xg.y); h.y = sigm_(xo.y) * tanhf(c.y);
    c.z = sigm_(xi.z) * tanhf(xg.z); h.z = sigm_(xo.z) * tanhf(c.z);
    c.w = sigm_(xi.w) * tanhf(xg.w); h.w = sigm_(xo.w) * tanhf(c.w);
    ((float4*)&Cp[(size_t)p * H])[lane] = c;
    ((float4*)&Hp[(size_t)p * H])[lane] = h;
}

// layer 1: H=128; 32 threads/node
__global__ void lstm_step1(const int* __restrict__ nbr, int t) {
    int cnt = d_suffix[t + 1];
    int idx = blockIdx.x * blockDim.x + threadIdx.x;
    int p = idx >> 5;
    if (p >= cnt) return;
    int lane = idx & 31;
    int node = d_perm[p];
    int nr = nbr[node * DMAXX + t];
    const float4* gb = (const float4*)&d_GB[(size_t)p * 512];
    const float4* gx = (const float4*)&d_G1[(size_t)nr * 512];
    float4 gi = gb[lane],       xi = gx[lane];
    float4 gf = gb[32 + lane],  xf = gx[32 + lane];
    float4 gg = gb[64 + lane],  xg = gx[64 + lane];
    float4 go = gb[96 + lane],  xo = gx[96 + lane];
    float4* cp = (float4*)&d_C1p[(size_t)p * 128];
    float4* hp = (float4*)&d_H1p[(size_t)p * 128];
    float4 c = cp[lane];
    float4 h;
    c.x = sigm_(gf.x + xf.x) * c.x + sigm_(gi.x + xi.x) * tanhf(gg.x + xg.x); h.x = sigm_(go.x + xo.x) * tanhf(c.x);
    c.y = sigm_(gf.y + xf.y) * c.y + sigm_(gi.y + xi.y) * tanhf(gg.y + xg.y); h.y = sigm_(go.y + xo.y) * tanhf(c.y);
    c.z = sigm_(gf.z + xf.z) * c.z + sigm_(gi.z + xi.z) * tanhf(gg.z + xg.z); h.z = sigm_(go.z + xo.z) * tanhf(c.z);
    c.w = sigm_(gf.w + xf.w) * c.w + sigm_(gi.w + xi.w) * tanhf(gg.w + xg.w); h.w = sigm_(go.w + xo.w) * tanhf(c.w);
    cp[lane] = c; hp[lane] = h;
}

// layer 2: H=256; 64 threads/node
__global__ void lstm_step2(const int* __restrict__ nbr, int t) {
    int cnt = d_suffix[t + 1];
    int idx = blockIdx.x * blockDim.x + threadIdx.x;
    int p = idx >> 6;
    if (p >= cnt) return;
    int lane = idx & 63;
    int node = d_perm[p];
    int nr = nbr[node * DMAXX + t];
    const float4* gb = (const float4*)&d_GB[(size_t)p * 1024];
    const float4* gx = (const float4*)&d_G2[(size_t)nr * 1024];
    float4 gi = gb[lane],        xi = gx[lane];
    float4 gf = gb[64 + lane],   xf = gx[64 + lane];
    float4 gg = gb[128 + lane],  xg = gx[128 + lane];
    float4 go = gb[192 + lane],  xo = gx[192 + lane];
    float4* cp = (float4*)&d_C2p[(size_t)p * 256];
    float4* hp = (float4*)&d_H2p[(size_t)p * 256];
    float4 c = cp[lane];
    float4 h;
    c.x = sigm_(gf.x + xf.x) * c.x + sigm_(gi.x + xi.x) * tanhf(gg.x + xg.x); h.x = sigm_(go.x + xo.x) * tanhf(c.x);
    c.y = sigm_(gf.y + xf.y) * c.y + sigm_(gi.y + xi.y) * tanhf(gg.y + xg.y); h.y = sigm_(go.y + xo.y) * tanhf(c.y);
    c.z = sigm_(gf.z + xf.z) * c.z + sigm_(gi.z + xi.z) * tanhf(gg.z + xg.z); h.z = sigm_(go.z + xo.z) * tanhf(c.z);
    c.w = sigm_(gf.w + xf.w) * c.w + sigm_(gi.w + xi.w) * tanhf(gg.w + xg.w); h.w = sigm_(go.w + xo.w) * tanhf(c.w);
    cp[lane] = c; hp[lane] = h;
}

// scatter permuted final hidden state back to natural node order
__global__ void k_scatter_h1() {
    int idx = blockIdx.x * blockDim.x + threadIdx.x;
    if (idx >= NN * 32) return;
    int p = idx >> 5, lane = idx & 31;
    int node = d_perm[p];
    ((float4*)d_M1)[node * 32 + lane] = ((const float4*)d_H1p)[p * 32 + lane];
}
__global__ void k_scatter_h2() {
    int idx = blockIdx.x * blockDim.x + threadIdx.x;
    if (idx >= NN * 64) return;
    int p = idx >> 6, lane = idx & 63;
    int node = d_perm[p];
    ((float4*)d_M2)[node * 64 + lane] = ((const float4*)d_H2p)[p * 64 + lane];
}

// ---------------- launch -----------------------------------------------------
extern "C" void kernel_launch(void* const* d_in, const int* in_sizes, int n_in,
                              void* d_out, int out_size) {
    const float* feat    = (const float*)d_in[0];
    const int*   nbr     = (const int*)  d_in[1];
    const int*   deg     = (const int*)  d_in[2];
    const float* Wih1    = (const float*)d_in[3];
    const float* Whh1    = (const float*)d_in[4];
    const float* bih1    = (const float*)d_in[5];
    const float* bhh1    = (const float*)d_in[6];
    const float* Wself1  = (const float*)d_in[7];
    const float* Wneigh1 = (const float*)d_in[8];
    const float* b1      = (const float*)d_in[9];
    const float* Wih2    = (const float*)d_in[10];
    const float* Whh2    = (const float*)d_in[11];
    const float* bih2    = (const float*)d_in[12];
    const float* bhh2    = (const float*)d_in[13];
    const float* Wself2  = (const float*)d_in[14];
    const float* Wneigh2 = (const float*)d_in[15];
    const float* b2      = (const float*)d_in[16];
    float* out = (float*)d_out;

    float *pG1, *pGB, *pH1, *pC1, *pM1, *pX1, *pG2, *pH2, *pC2, *pM2;
    int* pSuf;
    cudaGetSymbolAddress((void**)&pG1, d_G1);
    cudaGetSymbolAddress((void**)&pGB, d_GB);
    cudaGetSymbolAddress((void**)&pH1, d_H1p);
    cudaGetSymbolAddress((void**)&pC1, d_C1p);
    cudaGetSymbolAddress((void**)&pM1, d_M1);
    cudaGetSymbolAddress((void**)&pX1, d_X1);
    cudaGetSymbolAddress((void**)&pG2, d_G2);
    cudaGetSymbolAddress((void**)&pH2, d_H2p);
    cudaGetSymbolAddress((void**)&pC2, d_C2p);
    cudaGetSymbolAddress((void**)&pM2, d_M2);
    cudaGetSymbolAddress((void**)&pSuf, d_suffix);

    // dynamic smem sizes (2-stage): (BM+BN)*36*4*2 bytes
    const int SM_BIG = 2 * (128 + 128) * 36 * 4;   // 73728
    const int SM_SMALL = 2 * (128 + 64) * 36 * 4;  // 55296
    cudaFuncSetAttribute((const void*)tgemm_nt<128, 128, 2, 4, false, false>,
                         cudaFuncAttributeMaxDynamicSharedMemorySize, SM_BIG);
    cudaFuncSetAttribute((const void*)tgemm_nt<128, 128, 2, 4, true, true>,
                         cudaFuncAttributeMaxDynamicSharedMemorySize, SM_BIG);
    cudaFuncSetAttribute((const void*)tgemm_nt<128, 64, 2, 4, false, false>,
                         cudaFuncAttributeMaxDynamicSharedMemorySize, SM_SMALL);
    cudaFuncSetAttribute((const void*)tgemm_nt<128, 64, 2, 4, true, false>,
                         cudaFuncAttributeMaxDynamicSharedMemorySize, SM_SMALL);

    const int MB = (NN + 127) / 128;  // 235

    k_hist_zero<<<1, 32>>>();
    k_hist<<<(NN + 255) / 256, 256>>>(deg);
    k_scan<<<1, 1>>>();
    k_scatter<<<(NN + 255) / 256, 256>>>(deg);

    // ---------------- layer 1 ----------------
    tgemm_nt<128, 128, 2, 4, false, false><<<dim3(4, MB), 256, SM_BIG>>>(
        feat, Wih1, bih1, bhh1, pG1, NN, 512, 128, nullptr);
    lstm_step0<128><<<(NN * 32 + 255) / 256, 256>>>(pG1, nbr, pH1, pC1);
    for (int t = 1; t < DMAXX; t++) {
        tgemm_nt<128, 128, 2, 4, false, false><<<dim3(4, MB), 256, SM_BIG>>>(
            pH1, Whh1, nullptr, nullptr, pGB, NN, 512, 128, pSuf + (t + 1));
        lstm_step1<<<(NN * 32 + 255) / 256, 256>>>(nbr, t);
    }
    k_scatter_h1<<<(NN * 32 + 255) / 256, 256>>>();
    tgemm_nt<128, 128, 2, 4, false, false><<<dim3(2, MB), 256, SM_BIG>>>(
        feat, Wself1, b1, nullptr, pX1, NN, 256, 128, nullptr);
    tgemm_nt<128, 128, 2, 4, true, true><<<dim3(2, MB), 256, SM_BIG>>>(
        pM1, Wneigh1, nullptr, nullptr, pX1, NN, 256, 128, nullptr);

    // ---------------- layer 2 ----------------
    tgemm_nt<128, 128, 2, 4, false, false><<<dim3(8, MB), 256, SM_BIG>>>(
        pX1, Wih2, bih2, bhh2, pG2, NN, 1024, 256, nullptr);
    lstm_step0<256><<<(NN * 64 + 255) / 256, 256>>>(pG2, nbr, pH2, pC2);
    for (int t = 1; t < DMAXX; t++) {
        tgemm_nt<128, 128, 2, 4, false, false><<<dim3(8, MB), 256, SM_BIG>>>(
            pH2, Whh2, nullptr, nullptr, pGB, NN, 1024, 256, pSuf + (t + 1));
        lstm_step2<<<(NN * 64 + 255) / 256, 256>>>(nbr, t);
    }
    k_scatter_h2<<<(NN * 64 + 255) / 256, 256>>>();
    tgemm_nt<128, 64, 2, 4, false, false><<<dim3(1, MB), 256, SM_SMALL>>>(
        pX1, Wself2, b2, nullptr, out, NN, 64, 256, nullptr);
    tgemm_nt<128, 64, 2, 4, true, false><<<dim3(1, MB), 256, SM_SMALL>>>(
        pM2, Wneigh2, nullptr, nullptr, out, NN, 64, 256, nullptr);
}

// round 7
// speedup vs baseline: 1.4838x; 1.0308x over previous
#include <cuda_runtime.h>
#include <cstdint>

#define NN 30000
#define DMAXX 16

// ---------------- scratch (static device arrays; no cudaMalloc) -------------
__device__ __align__(16) float d_G1[(size_t)NN * 512];    // feat @ Wih1^T + biases
__device__ __align__(16) float d_GB[(size_t)NN * 1024];   // recurrent gate buffer (shared by both layers)
__device__ __align__(16) float d_H1p[(size_t)NN * 128];   // LSTM state, permuted order
__device__ __align__(16) float d_C1p[(size_t)NN * 128];
__device__ __align__(16) float d_M1[(size_t)NN * 128];    // aggregated neighbor hidden, natural order
__device__ __align__(16) float d_X1[(size_t)NN * 256];    // layer-1 output (post relu)
__device__ __align__(16) float d_G2[(size_t)NN * 1024];   // X1 @ Wih2^T + biases
__device__ __align__(16) float d_H2p[(size_t)NN * 256];
__device__ __align__(16) float d_C2p[(size_t)NN * 256];
__device__ __align__(16) float d_M2[(size_t)NN * 256];
__device__ int d_perm[NN];
__device__ int d_hist[17];
__device__ int d_suffix[18];   // d_suffix[t+1] = #nodes with deg > t
__device__ int d_offset[17];

// ---------------- degree counting sort (descending) -------------------------
__global__ void k_hist_zero() { if (threadIdx.x < 17) d_hist[threadIdx.x] = 0; }
__global__ void k_hist(const int* __restrict__ deg) {
    int n = blockIdx.x * blockDim.x + threadIdx.x;
    if (n < NN) atomicAdd(&d_hist[deg[n]], 1);
}
__global__ void k_scan() {
    d_suffix[17] = 0;
    for (int dd = 16; dd >= 1; --dd) d_suffix[dd] = d_suffix[dd + 1] + d_hist[dd];
    d_suffix[0] = d_suffix[1];
    for (int dd = 1; dd <= 16; ++dd) d_offset[dd] = d_suffix[dd + 1];
}
__global__ void k_scatter(const int* __restrict__ deg) {
    int n = blockIdx.x * blockDim.x + threadIdx.x;
    if (n < NN) {
        int pos = atomicAdd(&d_offset[deg[n]], 1);
        d_perm[pos] = n;
    }
}

// ---------------- tf32 helpers ----------------------------------------------
__device__ __forceinline__ uint32_t f2tf32(float x) {
    uint32_t y;
    asm("cvt.rna.tf32.f32 %0, %1;" : "=r"(y) : "f"(x));
    return y;
}
__device__ __forceinline__ void mma_tf32(float& c0, float& c1, float& c2, float& c3,
                                         uint32_t a0, uint32_t a1, uint32_t a2, uint32_t a3,
                                         uint32_t b0, uint32_t b1) {
    asm volatile(
        "mma.sync.aligned.m16n8k8.row.col.f32.tf32.tf32.f32 "
        "{%0,%1,%2,%3}, {%4,%5,%6,%7}, {%8,%9}, {%0,%1,%2,%3};"
        : "+f"(c0), "+f"(c1), "+f"(c2), "+f"(c3)
        : "r"(a0), "r"(a1), "r"(a2), "r"(a3), "r"(b0), "r"(b1));
}

// ---------------- tf32 GEMM: BK=32, reg prefetch + 2-stage smem --------------
// C[M,Nn] = A[M,K] @ W[Nn,K]^T (+bias0+bias1) (+=C) (relu). One sync per tile.
template<int BM, int BN, int WARPS_M, int WARPS_N, bool ACC, bool RELU>
__global__ __launch_bounds__(256)
void tgemm_nt(const float* __restrict__ A, const float* __restrict__ W,
              const float* __restrict__ bias0, const float* __restrict__ bias1,
              float* __restrict__ C, int M, int Nn, int K,
              const int* rowsDev) {
    constexpr int BK = 32;
    constexpr int LDS_ = BK + 4;           // 36, conflict-free fragment reads
    constexpr int WM = BM / WARPS_M;
    constexpr int WN = BN / WARPS_N;
    constexpr int MT = WM / 16;
    constexpr int NTT = WN / 8;
    constexpr int NTHR = WARPS_M * WARPS_N * 32;
    constexpr int AIT = BM * (BK / 4) / NTHR;
    constexpr int BIT = BN * (BK / 4) / NTHR;
    constexpr int ASTRIDE = BM * LDS_;
    constexpr int BSTRIDE = BN * LDS_;

    extern __shared__ uint32_t dynsmem[];
    uint32_t* AsBase = dynsmem;                 // [2][BM*LDS_]
    uint32_t* BsBase = dynsmem + 2 * ASTRIDE;   // [2][BN*LDS_]

    int rows = rowsDev ? *rowsDev : M;
    int rowBase = blockIdx.y * BM;
    if (rowBase >= rows) return;
    int colBase = blockIdx.x * BN;

    int tid = threadIdx.x;
    int wid = tid >> 5, lane = tid & 31;
    int wm = wid / WARPS_N, wn = wid % WARPS_N;
    int grp = lane >> 2, tg = lane & 3;

    float acc[MT][NTT][4];
#pragma unroll
    for (int i = 0; i < MT; i++)
#pragma unroll
        for (int j = 0; j < NTT; j++) {
            acc[i][j][0] = 0.f; acc[i][j][1] = 0.f; acc[i][j][2] = 0.f; acc[i][j][3] = 0.f;
        }

    float4 ra[AIT], rb[BIT];
    // prefetch tile 0 into registers
#pragma unroll
    for (int u = 0; u < AIT; u++) {
        int idx = tid + u * NTHR;
        int r = idx / (BK / 4), c4 = (idx % (BK / 4)) * 4;
        int gr = rowBase + r;
        ra[u] = (gr < rows) ? *(const float4*)&A[(size_t)gr * K + c4]
                            : make_float4(0.f, 0.f, 0.f, 0.f);
    }
#pragma unroll
    for (int u = 0; u < BIT; u++) {
        int idx = tid + u * NTHR;
        int r = idx / (BK / 4), c4 = (idx % (BK / 4)) * 4;
        rb[u] = *(const float4*)&W[(size_t)(colBase + r) * K + c4];
    }

    int stage = 0;
    for (int k0 = 0; k0 < K; k0 += BK, stage ^= 1) {
        uint32_t* As = AsBase + stage * ASTRIDE;
        uint32_t* Bs = BsBase + stage * BSTRIDE;

        // commit current registers (tile k0) to this stage
#pragma unroll
        for (int u = 0; u < AIT; u++) {
            int idx = tid + u * NTHR;
            int r = idx / (BK / 4), c4 = (idx % (BK / 4)) * 4;
            uint32_t* dst = &As[r * LDS_ + c4];
            dst[0] = f2tf32(ra[u].x); dst[1] = f2tf32(ra[u].y);
            dst[2] = f2tf32(ra[u].z); dst[3] = f2tf32(ra[u].w);
        }
#pragma unroll
        for (int u = 0; u < BIT; u++) {
            int idx = tid + u * NTHR;
            int r = idx / (BK / 4), c4 = (idx % (BK / 4)) * 4;
            uint32_t* dst = &Bs[r * LDS_ + c4];
            dst[0] = f2tf32(rb[u].x); dst[1] = f2tf32(rb[u].y);
            dst[2] = f2tf32(rb[u].z); dst[3] = f2tf32(rb[u].w);
        }
        __syncthreads();   // single barrier per tile

        // prefetch next tile (overlaps with MMAs below)
        int kn = k0 + BK;
        if (kn < K) {
#pragma unroll
            for (int u = 0; u < AIT; u++) {
                int idx = tid + u * NTHR;
                int r = idx / (BK / 4), c4 = (idx % (BK / 4)) * 4;
                int gr = rowBase + r;
                ra[u] = (gr < rows) ? *(const float4*)&A[(size_t)gr * K + kn + c4]
                                    : make_float4(0.f, 0.f, 0.f, 0.f);
            }
#pragma unroll
            for (int u = 0; u < BIT; u++) {
                int idx = tid + u * NTHR;
                int r = idx / (BK / 4), c4 = (idx % (BK / 4)) * 4;
                rb[u] = *(const float4*)&W[(size_t)(colBase + r) * K + kn + c4];
            }
        }

#pragma unroll
        for (int kk = 0; kk < BK; kk += 8) {
            uint32_t af[MT][4];
#pragma unroll
            for (int i = 0; i < MT; i++) {
                int r0 = wm * WM + i * 16 + grp;
                int c = kk + tg;
                af[i][0] = As[r0 * LDS_ + c];
                af[i][1] = As[(r0 + 8) * LDS_ + c];
                af[i][2] = As[r0 * LDS_ + c + 4];
                af[i][3] = As[(r0 + 8) * LDS_ + c + 4];
            }
            uint32_t bf[NTT][2];
#pragma unroll
            for (int j = 0; j < NTT; j++) {
                int n0 = wn * WN + j * 8 + grp;
                bf[j][0] = Bs[n0 * LDS_ + kk + tg];
                bf[j][1] = Bs[n0 * LDS_ + kk + tg + 4];
            }
#pragma unroll
            for (int i = 0; i < MT; i++)
#pragma unroll
                for (int j = 0; j < NTT; j++)
                    mma_tf32(acc[i][j][0], acc[i][j][1], acc[i][j][2], acc[i][j][3],
                             af[i][0], af[i][1], af[i][2], af[i][3], bf[j][0], bf[j][1]);
        }
    }

    // epilogue
#pragma unroll
    for (int i = 0; i < MT; i++) {
#pragma unroll
        for (int j = 0; j < NTT; j++) {
            int gc = colBase + wn * WN + j * 8 + 2 * tg;
            float b0v = 0.f, b1v = 0.f;
            if (bias0) { b0v += bias0[gc]; b1v += bias0[gc + 1]; }
            if (bias1) { b0v += bias1[gc]; b1v += bias1[gc + 1]; }
            int gr0 = rowBase + wm * WM + i * 16 + grp;
            if (gr0 < rows) {
                float v0 = acc[i][j][0] + b0v, v1 = acc[i][j][1] + b1v;
                float* p = &C[(size_t)gr0 * Nn + gc];
                if (ACC) { v0 += p[0]; v1 += p[1]; }
                if (RELU) { v0 = fmaxf(v0, 0.f); v1 = fmaxf(v1, 0.f); }
                *(float2*)p = make_float2(v0, v1);
            }
            int gr1 = gr0 + 8;
            if (gr1 < rows) {
                float v0 = acc[i][j][2] + b0v, v1 = acc[i][j][3] + b1v;
                float* p = &C[(size_t)gr1 * Nn + gc];
                if (ACC) { v0 += p[0]; v1 += p[1]; }
                if (RELU) { v0 = fmaxf(v0, 0.f); v1 = fmaxf(v1, 0.f); }
                *(float2*)p = make_float2(v0, v1);
            }
        }
    }
}

// ---------------- fast activations (hardware MUFU.TANH) ----------------------
__device__ __forceinline__ float tanh_f(float x) {
    float y;
    asm("tanh.approx.f32 %0, %1;" : "=f"(y) : "f"(x));
    return y;
}
// sigmoid(x) = 0.5*tanh(x/2) + 0.5  (exact identity; 1 MUFU + 1 FMA)
__device__ __forceinline__ float sigm_(float x) {
    return fmaf(tanh_f(0.5f * x), 0.5f, 0.5f);
}

// t = 0 step: H=0 so gates come straight from G; no GEMM needed. Writes C, H.
template<int H>
__global__ void lstm_step0(const float* __restrict__ G, const int* __restrict__ nbr,
                           float* __restrict__ Hp, float* __restrict__ Cp) {
    constexpr int TPN = H / 4;
    int cnt = d_suffix[1];
    int idx = blockIdx.x * blockDim.x + threadIdx.x;
    int p = idx / TPN;
    if (p >= cnt) return;
    int lane = idx % TPN;
    int node = d_perm[p];
    int nr = nbr[node * DMAXX];
    const float4* gx = (const float4*)&G[(size_t)nr * 4 * H];
    float4 xi = gx[lane], xg = gx[2 * TPN + lane], xo = gx[3 * TPN + lane];
    float4 c, h;
    c.x = sigm_(xi.x) * tanh_f(xg.x); h.x = sigm_(xo.x) * tanh_f(c.x);
    c.y = sigm_(xi.y) * tanh_f(xg.y); h.y = sigm_(xo.y) * tanh_f(c.y);
    c.z = sigm_(xi.z) * tanh_f(xg.z); h.z = sigm_(xo.z) * tanh_f(c.z);
    c.w = sigm_(xi.w) * tanh_f(xg.w); h.w = sigm_(xo.w) * tanh_f(c.w);
    ((float4*)&Cp[(size_t)p * H])[lane] = c;
    ((float4*)&Hp[(size_t)p * H])[lane] = h;
}

// layer 1: H=128; 32 threads/node
__global__ void lstm_step1(const int* __restrict__ nbr, int t) {
    int cnt = d_suffix[t + 1];
    int idx = blockIdx.x * blockDim.x + threadIdx.x;
    int p = idx >> 5;
    if (p >= cnt) return;
    int lane = idx & 31;
    int node = d_perm[p];
    int nr = nbr[node * DMAXX + t];
    const float4* gb = (const float4*)&d_GB[(size_t)p * 512];
    const float4* gx = (const float4*)&d_G1[(size_t)nr * 512];
    float4 gi = gb[lane],       xi = gx[lane];
    float4 gf = gb[32 + lane],  xf = gx[32 + lane];
    float4 gg = gb[64 + lane],  xg = gx[64 + lane];
    float4 go = gb[96 + lane],  xo = gx[96 + lane];
    float4* cp = (float4*)&d_C1p[(size_t)p * 128];
    float4* hp = (float4*)&d_H1p[(size_t)p * 128];
    float4 c = cp[lane];
    float4 h;
    c.x = sigm_(gf.x + xf.x) * c.x + sigm_(gi.x + xi.x) * tanh_f(gg.x + xg.x); h.x = sigm_(go.x + xo.x) * tanh_f(c.x);
    c.y = sigm_(gf.y + xf.y) * c.y + sigm_(gi.y + xi.y) * tanh_f(gg.y + xg.y); h.y = sigm_(go.y + xo.y) * tanh_f(c.y);
    c.z = sigm_(gf.z + xf.z) * c.z + sigm_(gi.z + xi.z) * tanh_f(gg.z + xg.z); h.z = sigm_(go.z + xo.z) * tanh_f(c.z);
    c.w = sigm_(gf.w + xf.w) * c.w + sigm_(gi.w + xi.w) * tanh_f(gg.w + xg.w); h.w = sigm_(go.w + xo.w) * tanh_f(c.w);
    cp[lane] = c; hp[lane] = h;
}

// layer 2: H=256; 64 threads/node
__global__ void lstm_step2(const int* __restrict__ nbr, int t) {
    int cnt = d_suffix[t + 1];
    int idx = blockIdx.x * blockDim.x + threadIdx.x;
    int p = idx >> 6;
    if (p >= cnt) return;
    int lane = idx & 63;
    int node = d_perm[p];
    int nr = nbr[node * DMAXX + t];
    const float4* gb = (const float4*)&d_GB[(size_t)p * 1024];
    const float4* gx = (const float4*)&d_G2[(size_t)nr * 1024];
    float4 gi = gb[lane],        xi = gx[lane];
    float4 gf = gb[64 + lane],   xf = gx[64 + lane];
    float4 gg = gb[128 + lane],  xg = gx[128 + lane];
    float4 go = gb[192 + lane],  xo = gx[192 + lane];
    float4* cp = (float4*)&d_C2p[(size_t)p * 256];
    float4* hp = (float4*)&d_H2p[(size_t)p * 256];
    float4 c = cp[lane];
    float4 h;
    c.x = sigm_(gf.x + xf.x) * c.x + sigm_(gi.x + xi.x) * tanh_f(gg.x + xg.x); h.x = sigm_(go.x + xo.x) * tanh_f(c.x);
    c.y = sigm_(gf.y + xf.y) * c.y + sigm_(gi.y + xi.y) * tanh_f(gg.y + xg.y); h.y = sigm_(go.y + xo.y) * tanh_f(c.y);
    c.z = sigm_(gf.z + xf.z) * c.z + sigm_(gi.z + xi.z) * tanh_f(gg.z + xg.z); h.z = sigm_(go.z + xo.z) * tanh_f(c.z);
    c.w = sigm_(gf.w + xf.w) * c.w + sigm_(gi.w + xi.w) * tanh_f(gg.w + xg.w); h.w = sigm_(go.w + xo.w) * tanh_f(c.w);
    cp[lane] = c; hp[lane] = h;
}

// scatter permuted final hidden state back to natural node order
__global__ void k_scatter_h1() {
    int idx = blockIdx.x * blockDim.x + threadIdx.x;
    if (idx >= NN * 32) return;
    int p = idx >> 5, lane = idx & 31;
    int node = d_perm[p];
    ((float4*)d_M1)[node * 32 + lane] = ((const float4*)d_H1p)[p * 32 + lane];
}
__global__ void k_scatter_h2() {
    int idx = blockIdx.x * blockDim.x + threadIdx.x;
    if (idx >= NN * 64) return;
    int p = idx >> 6, lane = idx & 63;
    int node = d_perm[p];
    ((float4*)d_M2)[node * 64 + lane] = ((const float4*)d_H2p)[p * 64 + lane];
}

// ---------------- launch -----------------------------------------------------
extern "C" void kernel_launch(void* const* d_in, const int* in_sizes, int n_in,
                              void* d_out, int out_size) {
    const float* feat    = (const float*)d_in[0];
    const int*   nbr     = (const int*)  d_in[1];
    const int*   deg     = (const int*)  d_in[2];
    const float* Wih1    = (const float*)d_in[3];
    const float* Whh1    = (const float*)d_in[4];
    const float* bih1    = (const float*)d_in[5];
    const float* bhh1    = (const float*)d_in[6];
    const float* Wself1  = (const float*)d_in[7];
    const float* Wneigh1 = (const float*)d_in[8];
    const float* b1      = (const float*)d_in[9];
    const float* Wih2    = (const float*)d_in[10];
    const float* Whh2    = (const float*)d_in[11];
    const float* bih2    = (const float*)d_in[12];
    const float* bhh2    = (const float*)d_in[13];
    const float* Wself2  = (const float*)d_in[14];
    const float* Wneigh2 = (const float*)d_in[15];
    const float* b2      = (const float*)d_in[16];
    float* out = (float*)d_out;

    float *pG1, *pGB, *pH1, *pC1, *pM1, *pX1, *pG2, *pH2, *pC2, *pM2;
    int* pSuf;
    cudaGetSymbolAddress((void**)&pG1, d_G1);
    cudaGetSymbolAddress((void**)&pGB, d_GB);
    cudaGetSymbolAddress((void**)&pH1, d_H1p);
    cudaGetSymbolAddress((void**)&pC1, d_C1p);
    cudaGetSymbolAddress((void**)&pM1, d_M1);
    cudaGetSymbolAddress((void**)&pX1, d_X1);
    cudaGetSymbolAddress((void**)&pG2, d_G2);
    cudaGetSymbolAddress((void**)&pH2, d_H2p);
    cudaGetSymbolAddress((void**)&pC2, d_C2p);
    cudaGetSymbolAddress((void**)&pM2, d_M2);
    cudaGetSymbolAddress((void**)&pSuf, d_suffix);

    // dynamic smem sizes (2-stage): (BM+BN)*36*4*2 bytes
    const int SM_BIG = 2 * (128 + 128) * 36 * 4;   // 73728
    const int SM_SMALL = 2 * (128 + 64) * 36 * 4;  // 55296
    cudaFuncSetAttribute((const void*)tgemm_nt<128, 128, 2, 4, false, false>,
                         cudaFuncAttributeMaxDynamicSharedMemorySize, SM_BIG);
    cudaFuncSetAttribute((const void*)tgemm_nt<128, 128, 2, 4, true, true>,
                         cudaFuncAttributeMaxDynamicSharedMemorySize, SM_BIG);
    cudaFuncSetAttribute((const void*)tgemm_nt<128, 64, 2, 4, false, false>,
                         cudaFuncAttributeMaxDynamicSharedMemorySize, SM_SMALL);
    cudaFuncSetAttribute((const void*)tgemm_nt<128, 64, 2, 4, true, false>,
                         cudaFuncAttributeMaxDynamicSharedMemorySize, SM_SMALL);

    const int MB = (NN + 127) / 128;  // 235

    k_hist_zero<<<1, 32>>>();
    k_hist<<<(NN + 255) / 256, 256>>>(deg);
    k_scan<<<1, 1>>>();
    k_scatter<<<(NN + 255) / 256, 256>>>(deg);

    // ---------------- layer 1 ----------------
    tgemm_nt<128, 128, 2, 4, false, false><<<dim3(4, MB), 256, SM_BIG>>>(
        feat, Wih1, bih1, bhh1, pG1, NN, 512, 128, nullptr);
    lstm_step0<128><<<(NN * 32 + 255) / 256, 256>>>(pG1, nbr, pH1, pC1);
    for (int t = 1; t < DMAXX; t++) {
        tgemm_nt<128, 128, 2, 4, false, false><<<dim3(4, MB), 256, SM_BIG>>>(
            pH1, Whh1, nullptr, nullptr, pGB, NN, 512, 128, pSuf + (t + 1));
        lstm_step1<<<(NN * 32 + 255) / 256, 256>>>(nbr, t);
    }
    k_scatter_h1<<<(NN * 32 + 255) / 256, 256>>>();
    tgemm_nt<128, 128, 2, 4, false, false><<<dim3(2, MB), 256, SM_BIG>>>(
        feat, Wself1, b1, nullptr, pX1, NN, 256, 128, nullptr);
    tgemm_nt<128, 128, 2, 4, true, true><<<dim3(2, MB), 256, SM_BIG>>>(
        pM1, Wneigh1, nullptr, nullptr, pX1, NN, 256, 128, nullptr);

    // ---------------- layer 2 ----------------
    tgemm_nt<128, 128, 2, 4, false, false><<<dim3(8, MB), 256, SM_BIG>>>(
        pX1, Wih2, bih2, bhh2, pG2, NN, 1024, 256, nullptr);
    lstm_step0<256><<<(NN * 64 + 255) / 256, 256>>>(pG2, nbr, pH2, pC2);
    for (int t = 1; t < DMAXX; t++) {
        tgemm_nt<128, 128, 2, 4, false, false><<<dim3(8, MB), 256, SM_BIG>>>(
            pH2, Whh2, nullptr, nullptr, pGB, NN, 1024, 256, pSuf + (t + 1));
        lstm_step2<<<(NN * 64 + 255) / 256, 256>>>(nbr, t);
    }
    k_scatter_h2<<<(NN * 64 + 255) / 256, 256>>>();
    tgemm_nt<128, 64, 2, 4, false, false><<<dim3(1, MB), 256, SM_SMALL>>>(
        pX1, Wself2, b2, nullptr, out, NN, 64, 256, nullptr);
    tgemm_nt<128, 64, 2, 4, true, false><<<dim3(1, MB), 256, SM_SMALL>>>(
        pM2, Wneigh2, nullptr, nullptr, out, NN, 64, 256, nullptr);
}

// round 9
// speedup vs baseline: 1.5476x; 1.0430x over previous
#include <cuda_runtime.h>
#include <cstdint>

#define NN 30000
#define DMAXX 16

// ---------------- scratch (static device arrays; no cudaMalloc) -------------
__device__ __align__(16) float d_G1[(size_t)NN * 512];    // feat @ Wih1^T + biases
__device__ __align__(16) float d_GB[(size_t)NN * 1024];   // recurrent gate buffer
__device__ __align__(16) float d_H1p[(size_t)NN * 128];   // LSTM state, permuted order (stored tf32-rounded)
__device__ __align__(16) float d_C1p[(size_t)NN * 128];
__device__ __align__(16) float d_M1[(size_t)NN * 128];    // aggregated neighbor hidden (rounded via H)
__device__ __align__(16) float d_X1[(size_t)NN * 256];    // layer-1 output (stored tf32-rounded)
__device__ __align__(16) float d_G2[(size_t)NN * 1024];   // X1 @ Wih2^T + biases
__device__ __align__(16) float d_H2p[(size_t)NN * 256];
__device__ __align__(16) float d_C2p[(size_t)NN * 256];
__device__ __align__(16) float d_M2[(size_t)NN * 256];
__device__ __align__(16) float d_Fr[(size_t)NN * 128];    // feat, tf32-rounded
// tf32-rounded weights
__device__ __align__(16) float d_Wih1r[512 * 128];
__device__ __align__(16) float d_Whh1r[512 * 128];
__device__ __align__(16) float d_Wself1r[256 * 128];
__device__ __align__(16) float d_Wneigh1r[256 * 128];
__device__ __align__(16) float d_Wih2r[1024 * 256];
__device__ __align__(16) float d_Whh2r[1024 * 256];
__device__ __align__(16) float d_Wself2r[64 * 256];
__device__ __align__(16) float d_Wneigh2r[64 * 256];
__device__ int d_perm[NN];
__device__ int d_hist[17];
__device__ int d_suffix[18];   // d_suffix[t+1] = #nodes with deg > t
__device__ int d_offset[17];

// ---------------- tf32 round helpers ----------------------------------------
__device__ __forceinline__ uint32_t f2tf32(float x) {
    uint32_t y;
    asm("cvt.rna.tf32.f32 %0, %1;" : "=r"(y) : "f"(x));
    return y;
}
__device__ __forceinline__ float rtf(float x) { return __uint_as_float(f2tf32(x)); }

// elementwise rna-round copy (n4 = element count / 4)
__global__ void k_round4(const float* __restrict__ in, float* __restrict__ out, int n4) {
    int i = blockIdx.x * blockDim.x + threadIdx.x;
    if (i < n4) {
        float4 v = ((const float4*)in)[i];
        v.x = rtf(v.x); v.y = rtf(v.y); v.z = rtf(v.z); v.w = rtf(v.w);
        ((float4*)out)[i] = v;
    }
}

// ---------------- degree counting sort (descending) -------------------------
__global__ void k_hist_zero() { if (threadIdx.x < 17) d_hist[threadIdx.x] = 0; }
__global__ void k_hist(const int* __restrict__ deg) {
    int n = blockIdx.x * blockDim.x + threadIdx.x;
    if (n < NN) atomicAdd(&d_hist[deg[n]], 1);
}
__global__ void k_scan() {
    d_suffix[17] = 0;
    for (int dd = 16; dd >= 1; --dd) d_suffix[dd] = d_suffix[dd + 1] + d_hist[dd];
    d_suffix[0] = d_suffix[1];
    for (int dd = 1; dd <= 16; ++dd) d_offset[dd] = d_suffix[dd + 1];
}
__global__ void k_scatter(const int* __restrict__ deg) {
    int n = blockIdx.x * blockDim.x + threadIdx.x;
    if (n < NN) {
        int pos = atomicAdd(&d_offset[deg[n]], 1);
        d_perm[pos] = n;
    }
}

// ---------------- mma + cp.async helpers -------------------------------------
__device__ __forceinline__ void mma_tf32(float& c0, float& c1, float& c2, float& c3,
                                         uint32_t a0, uint32_t a1, uint32_t a2, uint32_t a3,
                                         uint32_t b0, uint32_t b1) {
    asm volatile(
        "mma.sync.aligned.m16n8k8.row.col.f32.tf32.tf32.f32 "
        "{%0,%1,%2,%3}, {%4,%5,%6,%7}, {%8,%9}, {%0,%1,%2,%3};"
        : "+f"(c0), "+f"(c1), "+f"(c2), "+f"(c3)
        : "r"(a0), "r"(a1), "r"(a2), "r"(a3), "r"(b0), "r"(b1));
}
__device__ __forceinline__ void cp_async16(uint32_t dst_smem, const void* src, int src_bytes) {
    asm volatile("cp.async.cg.shared.global [%0], [%1], 16, %2;"
                 :: "r"(dst_smem), "l"(src), "r"(src_bytes));
}
__device__ __forceinline__ void cp_commit() { asm volatile("cp.async.commit_group;"); }
__device__ __forceinline__ void cp_wait0() { asm volatile("cp.async.wait_group 0;"); }

// ---------------- tf32 GEMM: BK=32, cp.async 2-stage pipeline ----------------
// Inputs must be pre-rounded to tf32 (rna) in gmem; loads are raw 16B copies.
template<int BM, int BN, int WARPS_M, int WARPS_N, bool ACC, bool RELU, bool ROUND>
__global__ __launch_bounds__(256, 2)
void tgemm_nt(const float* __restrict__ A, const float* __restrict__ W,
              const float* __restrict__ bias0, const float* __restrict__ bias1,
              float* __restrict__ C, int M, int Nn, int K,
              const int* rowsDev) {
    constexpr int BK = 32;
    constexpr int LDS_ = BK + 4;           // 36: conflict-free, 144B pitch (16B aligned)
    constexpr int WM = BM / WARPS_M;
    constexpr int WN = BN / WARPS_N;
    constexpr int MT = WM / 16;
    constexpr int NTT = WN / 8;
    constexpr int NTHR = WARPS_M * WARPS_N * 32;
    constexpr int AIT = BM * (BK / 4) / NTHR;
    constexpr int BIT = BN * (BK / 4) / NTHR;
    constexpr int ASTRIDE = BM * LDS_;
    constexpr int BSTRIDE = BN * LDS_;

    extern __shared__ uint32_t dynsmem[];
    uint32_t* AsBase = dynsmem;
    uint32_t* BsBase = dynsmem + 2 * ASTRIDE;
    const uint32_t sbase = (uint32_t)__cvta_generic_to_shared(dynsmem);
    const uint32_t sbaseB = sbase + 2 * ASTRIDE * 4;

    int rows = rowsDev ? *rowsDev : M;
    int rowBase = blockIdx.y * BM;
    if (rowBase >= rows) return;
    int colBase = blockIdx.x * BN;

    int tid = threadIdx.x;
    int wid = tid >> 5, lane = tid & 31;
    int wm = wid / WARPS_N, wn = wid % WARPS_N;
    int grp = lane >> 2, tg = lane & 3;

    float acc[MT][NTT][4];
#pragma unroll
    for (int i = 0; i < MT; i++)
#pragma unroll
        for (int j = 0; j < NTT; j++) {
            acc[i][j][0] = 0.f; acc[i][j][1] = 0.f; acc[i][j][2] = 0.f; acc[i][j][3] = 0.f;
        }

    const int ar = tid / (BK / 4);
    const int ac4 = (tid % (BK / 4)) * 4;
    constexpr int ARSTEP = NTHR / (BK / 4);

    auto issue_tile = [&](int k0, int stg) {
#pragma unroll
        for (int u = 0; u < AIT; u++) {
            int r = ar + u * ARSTEP;
            int gr = rowBase + r;
            uint32_t dst = sbase + (uint32_t)(stg * ASTRIDE + r * LDS_ + ac4) * 4;
            cp_async16(dst, &A[(size_t)gr * K + k0 + ac4], (gr < rows) ? 16 : 0);
        }
#pragma unroll
        for (int u = 0; u < BIT; u++) {
            int r = ar + u * ARSTEP;
            uint32_t dst = sbaseB + (uint32_t)(stg * BSTRIDE + r * LDS_ + ac4) * 4;
            cp_async16(dst, &W[(size_t)(colBase + r) * K + k0 + ac4], 16);
        }
        cp_commit();
    };

    issue_tile(0, 0);

    int stage = 0;
    for (int k0 = 0; k0 < K; k0 += BK, stage ^= 1) {
        cp_wait0();
        __syncthreads();

        int kn = k0 + BK;
        if (kn < K) issue_tile(kn, stage ^ 1);

        uint32_t* As = AsBase + stage * ASTRIDE;
        uint32_t* Bs = BsBase + stage * BSTRIDE;

#pragma unroll
        for (int kk = 0; kk < BK; kk += 8) {
            uint32_t af[MT][4];
#pragma unroll
            for (int i = 0; i < MT; i++) {
                int r0 = wm * WM + i * 16 + grp;
                int c = kk + tg;
                af[i][0] = As[r0 * LDS_ + c];
                af[i][1] = As[(r0 + 8) * LDS_ + c];
                af[i][2] = As[r0 * LDS_ + c + 4];
                af[i][3] = As[(r0 + 8) * LDS_ + c + 4];
            }
            uint32_t bf[NTT][2];
#pragma unroll
            for (int j = 0; j < NTT; j++) {
                int n0 = wn * WN + j * 8 + grp;
                bf[j][0] = Bs[n0 * LDS_ + kk + tg];
                bf[j][1] = Bs[n0 * LDS_ + kk + tg + 4];
            }
#pragma unroll
            for (int i = 0; i < MT; i++)
#pragma unroll
                for (int j = 0; j < NTT; j++)
                    mma_tf32(acc[i][j][0], acc[i][j][1], acc[i][j][2], acc[i][j][3],
                             af[i][0], af[i][1], af[i][2], af[i][3], bf[j][0], bf[j][1]);
        }
        __syncthreads();
    }

    // epilogue
#pragma unroll
    for (int i = 0; i < MT; i++) {
#pragma unroll
        for (int j = 0; j < NTT; j++) {
            int gc = colBase + wn * WN + j * 8 + 2 * tg;
            float b0v = 0.f, b1v = 0.f;
            if (bias0) { b0v += bias0[gc]; b1v += bias0[gc + 1]; }
            if (bias1) { b0v += bias1[gc]; b1v += bias1[gc + 1]; }
            int gr0 = rowBase + wm * WM + i * 16 + grp;
            if (gr0 < rows) {
                float v0 = acc[i][j][0] + b0v, v1 = acc[i][j][1] + b1v;
                float* p = &C[(size_t)gr0 * Nn + gc];
                if (ACC) { v0 += p[0]; v1 += p[1]; }
                if (RELU) { v0 = fmaxf(v0, 0.f); v1 = fmaxf(v1, 0.f); }
                if (ROUND) { v0 = rtf(v0); v1 = rtf(v1); }
                *(float2*)p = make_float2(v0, v1);
            }
            int gr1 = gr0 + 8;
            if (gr1 < rows) {
                float v0 = acc[i][j][2] + b0v, v1 = acc[i][j][3] + b1v;
                float* p = &C[(size_t)gr1 * Nn + gc];
                if (ACC) { v0 += p[0]; v1 += p[1]; }
                if (RELU) { v0 = fmaxf(v0, 0.f); v1 = fmaxf(v1, 0.f); }
                if (ROUND) { v0 = rtf(v0); v1 = rtf(v1); }
                *(float2*)p = make_float2(v0, v1);
            }
        }
    }
}

// ---------------- fast activations (hardware MUFU.TANH) ----------------------
__device__ __forceinline__ float tanh_f(float x) {
    float y;
    asm("tanh.approx.f32 %0, %1;" : "=f"(y) : "f"(x));
    return y;
}
__device__ __forceinline__ float sigm_(float x) {
    return fmaf(tanh_f(0.5f * x), 0.5f, 0.5f);
}

// t = 0 step: gates come straight from G. C full precision; H stored rounded.
template<int H>
__global__ void lstm_step0(const float* __restrict__ G, const int* __restrict__ nbr,
                           float* __restrict__ Hp, float* __restrict__ Cp) {
    constexpr int TPN = H / 4;
    int cnt = d_suffix[1];
    int idx = blockIdx.x * blockDim.x + threadIdx.x;
    int p = idx / TPN;
    if (p >= cnt) return;
    int lane = idx % TPN;
    int node = d_perm[p];
    int nr = nbr[node * DMAXX];
    const float4* gx = (const float4*)&G[(size_t)nr * 4 * H];
    float4 xi = gx[lane], xg = gx[2 * TPN + lane], xo = gx[3 * TPN + lane];
    float4 c, h;
    c.x = sigm_(xi.x) * tanh_f(xg.x); h.x = rtf(sigm_(xo.x) * tanh_f(c.x));
    c.y = sigm_(xi.y) * tanh_f(xg.y); h.y = rtf(sigm_(xo.y) * tanh_f(c.y));
    c.z = sigm_(xi.z) * tanh_f(xg.z); h.z = rtf(sigm_(xo.z) * tanh_f(c.z));
    c.w = sigm_(xi.w) * tanh_f(xg.w); h.w = rtf(sigm_(xo.w) * tanh_f(c.w));
    ((float4*)&Cp[(size_t)p * H])[lane] = c;
    ((float4*)&Hp[(size_t)p * H])[lane] = h;
}

// layer 1: H=128; 32 threads/node. H stored rounded, C full precision.
__global__ void lstm_step1(const int* __restrict__ nbr, int t) {
    int cnt = d_suffix[t + 1];
    int idx = blockIdx.x * blockDim.x + threadIdx.x;
    int p = idx >> 5;
    if (p >= cnt) return;
    int lane = idx & 31;
    int node = d_perm[p];
    int nr = nbr[node * DMAXX + t];
    const float4* gb = (const float4*)&d_GB[(size_t)p * 512];
    const float4* gx = (const float4*)&d_G1[(size_t)nr * 512];
    float4 gi = gb[lane],       xi = gx[lane];
    float4 gf = gb[32 + lane],  xf = gx[32 + lane];
    float4 gg = gb[64 + lane],  xg = gx[64 + lane];
    float4 go = gb[96 + lane],  xo = gx[96 + lane];
    float4* cp = (float4*)&d_C1p[(size_t)p * 128];
    float4* hp = (float4*)&d_H1p[(size_t)p * 128];
    float4 c = cp[lane];
    float4 h;
    c.x = sigm_(gf.x + xf.x) * c.x + sigm_(gi.x + xi.x) * tanh_f(gg.x + xg.x); h.x = rtf(sigm_(go.x + xo.x) * tanh_f(c.x));
    c.y = sigm_(gf.y + xf.y) * c.y + sigm_(gi.y + xi.y) * tanh_f(gg.y + xg.y); h.y = rtf(sigm_(go.y + xo.y) * tanh_f(c.y));
    c.z = sigm_(gf.z + xf.z) * c.z + sigm_(gi.z + xi.z) * tanh_f(gg.z + xg.z); h.z = rtf(sigm_(go.z + xo.z) * tanh_f(c.z));
    c.w = sigm_(gf.w + xf.w) * c.w + sigm_(gi.w + xi.w) * tanh_f(gg.w + xg.w); h.w = rtf(sigm_(go.w + xo.w) * tanh_f(c.w));
    cp[lane] = c; hp[lane] = h;
}

// layer 2: H=256; 64 threads/node
__global__ void lstm_step2(const int* __restrict__ nbr, int t) {
    int cnt = d_suffix[t + 1];
    int idx = blockIdx.x * blockDim.x + threadIdx.x;
    int p = idx >> 6;
    if (p >= cnt) return;
    int lane = idx & 63;
    int node = d_perm[p];
    int nr = nbr[node * DMAXX + t];
    const float4* gb = (const float4*)&d_GB[(size_t)p * 1024];
    const float4* gx = (const float4*)&d_G2[(size_t)nr * 1024];
    float4 gi = gb[lane],        xi = gx[lane];
    float4 gf = gb[64 + lane],   xf = gx[64 + lane];
    float4 gg = gb[128 + lane],  xg = gx[128 + lane];
    float4 go = gb[192 + lane],  xo = gx[192 + lane];
    float4* cp = (float4*)&d_C2p[(size_t)p * 256];
    float4* hp = (float4*)&d_H2p[(size_t)p * 256];
    float4 c = cp[lane];
    float4 h;
    c.x = sigm_(gf.x + xf.x) * c.x + sigm_(gi.x + xi.x) * tanh_f(gg.x + xg.x); h.x = rtf(sigm_(go.x + xo.x) * tanh_f(c.x));
    c.y = sigm_(gf.y + xf.y) * c.y + sigm_(gi.y + xi.y) * tanh_f(gg.y + xg.y); h.y = rtf(sigm_(go.y + xo.y) * tanh_f(c.y));
    c.z = sigm_(gf.z + xf.z) * c.z + sigm_(gi.z + xi.z) * tanh_f(gg.z + xg.z); h.z = rtf(sigm_(go.z + xo.z) * tanh_f(c.z));
    c.w = sigm_(gf.w + xf.w) * c.w + sigm_(gi.w + xi.w) * tanh_f(gg.w + xg.w); h.w = rtf(sigm_(go.w + xo.w) * tanh_f(c.w));
    cp[lane] = c; hp[lane] = h;
}

// scatter permuted final hidden state back to natural node order
__global__ void k_scatter_h1() {
    int idx = blockIdx.x * blockDim.x + threadIdx.x;
    if (idx >= NN * 32) return;
    int p = idx >> 5, lane = idx & 31;
    int node = d_perm[p];
    ((float4*)d_M1)[node * 32 + lane] = ((const float4*)d_H1p)[p * 32 + lane];
}
__global__ void k_scatter_h2() {
    int idx = blockIdx.x * blockDim.x + threadIdx.x;
    if (idx >= NN * 64) return;
    int p = idx >> 6, lane = idx & 63;
    int node = d_perm[p];
    ((float4*)d_M2)[node * 64 + lane] = ((const float4*)d_H2p)[p * 64 + lane];
}

// ---------------- launch -----------------------------------------------------
extern "C" void kernel_launch(void* const* d_in, const int* in_sizes, int n_in,
                              void* d_out, int out_size) {
    const float* feat    = (const float*)d_in[0];
    const int*   nbr     = (const int*)  d_in[1];
    const int*   deg     = (const int*)  d_in[2];
    const float* Wih1    = (const float*)d_in[3];
    const float* Whh1    = (const float*)d_in[4];
    const float* bih1    = (const float*)d_in[5];
    const float* bhh1    = (const float*)d_in[6];
    const float* Wself1  = (const float*)d_in[7];
    const float* Wneigh1 = (const float*)d_in[8];
    const float* b1      = (const float*)d_in[9];
    const float* Wih2    = (const float*)d_in[10];
    const float* Whh2    = (const float*)d_in[11];
    const float* bih2    = (const float*)d_in[12];
    const float* bhh2    = (const float*)d_in[13];
    const float* Wself2  = (const float*)d_in[14];
    const float* Wneigh2 = (const float*)d_in[15];
    const float* b2      = (const float*)d_in[16];
    float* out = (float*)d_out;

    float *pG1, *pGB, *pH1, *pC1, *pM1, *pX1, *pG2, *pH2, *pC2, *pM2, *pFr;
    float *pWih1r, *pWhh1r, *pWself1r, *pWneigh1r, *pWih2r, *pWhh2r, *pWself2r, *pWneigh2r;
    int* pSuf;
    cudaGetSymbolAddress((void**)&pG1, d_G1);
    cudaGetSymbolAddress((void**)&pGB, d_GB);
    cudaGetSymbolAddress((void**)&pH1, d_H1p);
    cudaGetSymbolAddress((void**)&pC1, d_C1p);
    cudaGetSymbolAddress((void**)&pM1, d_M1);
    cudaGetSymbolAddress((void**)&pX1, d_X1);
    cudaGetSymbolAddress((void**)&pG2, d_G2);
    cudaGetSymbolAddress((void**)&pH2, d_H2p);
    cudaGetSymbolAddress((void**)&pC2, d_C2p);
    cudaGetSymbolAddress((void**)&pM2, d_M2);
    cudaGetSymbolAddress((void**)&pFr, d_Fr);
    cudaGetSymbolAddress((void**)&pWih1r, d_Wih1r);
    cudaGetSymbolAddress((void**)&pWhh1r, d_Whh1r);
    cudaGetSymbolAddress((void**)&pWself1r, d_Wself1r);
    cudaGetSymbolAddress((void**)&pWneigh1r, d_Wneigh1r);
    cudaGetSymbolAddress((void**)&pWih2r, d_Wih2r);
    cudaGetSymbolAddress((void**)&pWhh2r, d_Whh2r);
    cudaGetSymbolAddress((void**)&pWself2r, d_Wself2r);
    cudaGetSymbolAddress((void**)&pWneigh2r, d_Wneigh2r);
    cudaGetSymbolAddress((void**)&pSuf, d_suffix);

    const int SM_BIG = 2 * (128 + 128) * 36 * 4;   // 73728
    const int SM_SMALL = 2 * (128 + 64) * 36 * 4;  // 55296
    cudaFuncSetAttribute((const void*)tgemm_nt<128, 128, 2, 4, false, false, false>,
                         cudaFuncAttributeMaxDynamicSharedMemorySize, SM_BIG);
    cudaFuncSetAttribute((const void*)tgemm_nt<128, 128, 2, 4, true, true, true>,
                         cudaFuncAttributeMaxDynamicSharedMemorySize, SM_BIG);
    cudaFuncSetAttribute((const void*)tgemm_nt<128, 64, 2, 4, false, false, false>,
                         cudaFuncAttributeMaxDynamicSharedMemorySize, SM_SMALL);
    cudaFuncSetAttribute((const void*)tgemm_nt<128, 64, 2, 4, true, false, false>,
                         cudaFuncAttributeMaxDynamicSharedMemorySize, SM_SMALL);

    const int MB = (NN + 127) / 128;  // 235

    // pre-round inputs to tf32 (rna) so raw cp.async loads match cvt.rna numerics
    k_round4<<<(NN * 32 + 255) / 256, 256>>>(feat, pFr, NN * 32);
    k_round4<<<(512 * 32 + 255) / 256, 256>>>(Wih1, pWih1r, 512 * 32);
    k_round4<<<(512 * 32 + 255) / 256, 256>>>(Whh1, pWhh1r, 512 * 32);
    k_round4<<<(256 * 32 + 255) / 256, 256>>>(Wself1, pWself1r, 256 * 32);
    k_round4<<<(256 * 32 + 255) / 256, 256>>>(Wneigh1, pWneigh1r, 256 * 32);
    k_round4<<<(1024 * 64 + 255) / 256, 256>>>(Wih2, pWih2r, 1024 * 64);
    k_round4<<<(1024 * 64 + 255) / 256, 256>>>(Whh2, pWhh2r, 1024 * 64);
    k_round4<<<(64 * 64 + 255) / 256, 256>>>(Wself2, pWself2r, 64 * 64);
    k_round4<<<(64 * 64 + 255) / 256, 256>>>(Wneigh2, pWneigh2r, 64 * 64);

    k_hist_zero<<<1, 32>>>();
    k_hist<<<(NN + 255) / 256, 256>>>(deg);
    k_scan<<<1, 1>>>();
    k_scatter<<<(NN + 255) / 256, 256>>>(deg);

    // ---------------- layer 1 ----------------
    tgemm_nt<128, 128, 2, 4, false, false, false><<<dim3(4, MB), 256, SM_BIG>>>(
        pFr, pWih1r, bih1, bhh1, pG1, NN, 512, 128, nullptr);
    lstm_step0<128><<<(NN * 32 + 255) / 256, 256>>>(pG1, nbr, pH1, pC1);
    for (int t = 1; t < DMAXX; t++) {
        tgemm_nt<128, 128, 2, 4, false, false, false><<<dim3(4, MB), 256, SM_BIG>>>(
            pH1, pWhh1r, nullptr, nullptr, pGB, NN, 512, 128, pSuf + (t + 1));
        lstm_step1<<<(NN * 32 + 255) / 256, 256>>>(nbr, t);
    }
    k_scatter_h1<<<(NN * 32 + 255) / 256, 256>>>();
    tgemm_nt<128, 128, 2, 4, false, false, false><<<dim3(2, MB), 256, SM_BIG>>>(
        pFr, pWself1r, b1, nullptr, pX1, NN, 256, 128, nullptr);
    tgemm_nt<128, 128, 2, 4, true, true, true><<<dim3(2, MB), 256, SM_BIG>>>(
        pM1, pWneigh1r, nullptr, nullptr, pX1, NN, 256, 128, nullptr);

    // ---------------- layer 2 ----------------
    tgemm_nt<128, 128, 2, 4, false, false, false><<<dim3(8, MB), 256, SM_BIG>>>(
        pX1, pWih2r, bih2, bhh2, pG2, NN, 1024, 256, nullptr);
    lstm_step0<256><<<(NN * 64 + 255) / 256, 256>>>(pG2, nbr, pH2, pC2);
    for (int t = 1; t < DMAXX; t++) {
        tgemm_nt<128, 128, 2, 4, false, false, false><<<dim3(8, MB), 256, SM_BIG>>>(
            pH2, pWhh2r, nullptr, nullptr, pGB, NN, 1024, 256, pSuf + (t + 1));
        lstm_step2<<<(NN * 64 + 255) / 256, 256>>>(nbr, t);
    }
    k_scatter_h2<<<(NN * 64 + 255) / 256, 256>>>();
    tgemm_nt<128, 64, 2, 4, false, false, false><<<dim3(1, MB), 256, SM_SMALL>>>(
        pX1, pWself2r, b2, nullptr, out, NN, 64, 256, nullptr);
    tgemm_nt<128, 64, 2, 4, true, false, false><<<dim3(1, MB), 256, SM_SMALL>>>(
        pM2, pWneigh2r, nullptr, nullptr, out, NN, 64, 256, nullptr);
}